// round 11
// baseline (speedup 1.0000x reference)
#include <cuda_runtime.h>

#define Bb 4
#define Ll 1024
#define Hh 128
#define Ee 128
#define Nn 128
#define ML (Bb*Ll)   // 4096
#define CH 32        // number of L-chunks
#define CS 32        // chunk size (CH*CS == Ll)

// ---------------- scratch (device globals: no allocations allowed) ----------------
__device__ float g_x[Bb*Ll*Ee];      // pre-conv x
__device__ float g_zs[Bb*Ll*Ee];     // silu(z)
__device__ float g_xc[Bb*Ll*Ee];     // post-conv silu(x)
__device__ float g_delta[Bb*Ll*Nn];  // softplus'd
__device__ float g_Braw[Bb*Ll*Nn];
__device__ float g_C[Bb*Ll*Hh];
__device__ float g_y[Bb*Ll*Hh];      // gated scan output (input to GEMM3)
__device__ float g_S[Bb*Ll*Hh];      // local (then full) n-sums
__device__ float g_cumd[Bb*Ll*Nn];   // within-chunk inclusive cumsum of delta
__device__ float g_hE[Bb*CH*Nn*Hh];  // chunk-end local states [b][k][n][c]
__device__ float g_h0[Bb*CH*Nn*Hh];  // chunk-start true states [b][k][n][c]

__device__ __forceinline__ float silu_(float x){ return x / (1.f + __expf(-x)); }
__device__ __forceinline__ float softplus_(float x){ return x > 20.f ? x : log1pf(__expf(x)); }
__device__ __forceinline__ float ex2f(float x){ float r; asm("ex2.approx.ftz.f32 %0, %1;" : "=f"(r) : "f"(x)); return r; }

// ---------------- generic 64x64-tile SGEMM, K=128, fused epilogues (R4-exact) ------
template<int EPI>
__global__ __launch_bounds__(256) void gemm_kernel(
    const float* __restrict__ Ain, const float* __restrict__ Wp,
    const float* __restrict__ bias, float* __restrict__ Cout, int ldN)
{
    __shared__ __align__(16) float As[64][68];   // [row][k]
    __shared__ __align__(16) float Bs[64][64];   // [k][col]
    const float* Ap = (EPI == 1) ? Ain : (EPI == 2 ? g_xc : g_y);

    int tid = threadIdx.x;
    int ty = tid >> 4, tx = tid & 15;
    int row0 = blockIdx.x * 64;
    int col0 = blockIdx.y * 64;

    float acc[4][4];
    #pragma unroll
    for (int i = 0; i < 4; i++)
        #pragma unroll
        for (int j = 0; j < 4; j++) acc[i][j] = 0.f;

    #pragma unroll
    for (int kb = 0; kb < 2; ++kb) {
        #pragma unroll
        for (int i = 0; i < 4; ++i) {
            int f = tid + i * 256;
            int r = f >> 4, kq = f & 15;
            float4 v = *(const float4*)&Ap[(size_t)(row0 + r) * 128 + kb * 64 + kq * 4];
            *(float4*)&As[r][kq * 4] = v;
        }
        #pragma unroll
        for (int i = 0; i < 4; ++i) {
            int f = tid + i * 256;
            int k = f >> 4, nq = f & 15;
            float4 v = *(const float4*)&Wp[(size_t)(kb * 64 + k) * ldN + col0 + nq * 4];
            *(float4*)&Bs[k][nq * 4] = v;
        }
        __syncthreads();
        #pragma unroll 16
        for (int k = 0; k < 64; ++k) {
            float4 bv = *(float4*)&Bs[k][tx * 4];
            float a0 = As[ty * 4 + 0][k];
            float a1 = As[ty * 4 + 1][k];
            float a2 = As[ty * 4 + 2][k];
            float a3 = As[ty * 4 + 3][k];
            acc[0][0] = fmaf(a0, bv.x, acc[0][0]); acc[0][1] = fmaf(a0, bv.y, acc[0][1]);
            acc[0][2] = fmaf(a0, bv.z, acc[0][2]); acc[0][3] = fmaf(a0, bv.w, acc[0][3]);
            acc[1][0] = fmaf(a1, bv.x, acc[1][0]); acc[1][1] = fmaf(a1, bv.y, acc[1][1]);
            acc[1][2] = fmaf(a1, bv.z, acc[1][2]); acc[1][3] = fmaf(a1, bv.w, acc[1][3]);
            acc[2][0] = fmaf(a2, bv.x, acc[2][0]); acc[2][1] = fmaf(a2, bv.y, acc[2][1]);
            acc[2][2] = fmaf(a2, bv.z, acc[2][2]); acc[2][3] = fmaf(a2, bv.w, acc[2][3]);
            acc[3][0] = fmaf(a3, bv.x, acc[3][0]); acc[3][1] = fmaf(a3, bv.y, acc[3][1]);
            acc[3][2] = fmaf(a3, bv.z, acc[3][2]); acc[3][3] = fmaf(a3, bv.w, acc[3][3]);
        }
        __syncthreads();
    }

    #pragma unroll
    for (int i = 0; i < 4; ++i) {
        int row = row0 + ty * 4 + i;
        #pragma unroll
        for (int j = 0; j < 4; ++j) {
            int col = col0 + tx * 4 + j;
            float v = acc[i][j] + bias[col];
            if (EPI == 1) {
                if (col < 128) g_x[(size_t)row * 128 + col] = v;
                else           g_zs[(size_t)row * 128 + col - 128] = silu_(v);
            } else if (EPI == 2) {
                if (col < 128)      g_delta[(size_t)row * 128 + col] = softplus_(v);
                else if (col < 256) g_Braw[(size_t)row * 128 + col - 128] = v;
                else                g_C[(size_t)row * 128 + col - 256] = v;
            } else {
                Cout[(size_t)row * 128 + col] = v;
            }
        }
    }
}

// ---------------- depthwise conv3 (+bias, silu) ----------------
__global__ void conv_kernel(const float* __restrict__ cw, const float* __restrict__ cb)
{
    int idx = blockIdx.x * blockDim.x + threadIdx.x;
    if (idx >= Bb * Ll * Ee) return;
    int e = idx & 127;
    int t = (idx >> 7) & (Ll - 1);
    float w0 = cw[e * 3 + 0], w1 = cw[e * 3 + 1], w2 = cw[e * 3 + 2];
    float xm = g_x[idx];
    float xl = (t > 0)      ? g_x[idx - 128] : 0.f;
    float xr = (t < Ll - 1) ? g_x[idx + 128] : 0.f;
    float v = fmaf(w0, xl, fmaf(w1, xm, fmaf(w2, xr, cb[e])));
    g_xc[idx] = silu_(v);
}

// ---------------- Pass 1: per-chunk local scan, barrier-free shuffle reduce --------
// grid (4, CH, Bb). warp w owns c = cg*32 + w*4 + j; lane ln owns n = 4ln..4ln+3.
// n-sum per (t, c) is intra-warp: xor-8/16 butterfly on 4 partials, group-select,
// xor-1/2/4. No barriers in the t-loop.
__global__ __launch_bounds__(256) void scan_local_kernel(const float* __restrict__ A_log)
{
    __shared__ __align__(16) float smd[16][128];
    __shared__ __align__(16) float smb[16][128];
    __shared__ __align__(16) float smx[16][32];

    int b  = blockIdx.z;
    int k  = blockIdx.y;
    int cg = blockIdx.x;
    int tid = threadIdx.x;
    int w = tid >> 5, ln = tid & 31;

    float Ac2[4];
    #pragma unroll
    for (int j = 0; j < 4; ++j)
        Ac2[j] = -__expf(A_log[cg * 32 + w * 4 + j]) * 1.44269504f;

    const float4* del4 = (const float4*)(g_delta + (size_t)b * Ll * Nn);
    const float4* br4  = (const float4*)(g_Braw  + (size_t)b * Ll * Nn);
    const float* xcb   = g_xc + (size_t)b * Ll * Ee + cg * 32;

    float h[4][4];
    #pragma unroll
    for (int j = 0; j < 4; ++j)
        #pragma unroll
        for (int i = 0; i < 4; ++i) h[j][i] = 0.f;

    float dc = 0.f;
    bool do_cum = (cg == 0) && (tid < 128);
    int g = ln >> 3;                   // j-group this lane reduces for
    float* sout = g_S + (size_t)b * Ll * Hh + cg * 32 + w * 4 + g;

    for (int t0 = k * CS; t0 < (k + 1) * CS; t0 += 16) {
        #pragma unroll
        for (int i = 0; i < 2; ++i) {
            int idx = tid + i * 256;
            float4 d = del4[t0 * 32 + idx];
            float4 r = br4[t0 * 32 + idx];
            ((float4*)smd)[idx] = d;
            float4 p; p.x = d.x * r.x; p.y = d.y * r.y; p.z = d.z * r.z; p.w = d.w * r.w;
            ((float4*)smb)[idx] = p;
        }
        if (tid < 128) {
            int tt = tid >> 3, q = tid & 7;
            *(float4*)&smx[tt][q * 4] = *(const float4*)&xcb[(size_t)(t0 + tt) * Ee + q * 4];
        }
        __syncthreads();

        if (do_cum) {
            float* gout = g_cumd + (size_t)b * Ll * Nn + (size_t)t0 * Nn + tid;
            #pragma unroll
            for (int tl = 0; tl < 16; ++tl) { dc += smd[tl][tid]; gout[tl * 128] = dc; }
        }

        #pragma unroll
        for (int tl = 0; tl < 16; ++tl) {
            float4 d4 = *(float4*)&smd[tl][ln * 4];
            float4 b4 = *(float4*)&smb[tl][ln * 4];
            float4 x4 = *(float4*)&smx[tl][w * 4];
            float dn[4] = {d4.x, d4.y, d4.z, d4.w};
            float bn[4] = {b4.x, b4.y, b4.z, b4.w};
            float xs[4] = {x4.x, x4.y, x4.z, x4.w};
            float pj[4];
            #pragma unroll
            for (int j = 0; j < 4; ++j) {
                #pragma unroll
                for (int i = 0; i < 4; ++i) {
                    float e = ex2f(dn[i] * Ac2[j]);
                    h[j][i] = fmaf(e, h[j][i], bn[i] * xs[j]);
                }
                pj[j] = (h[j][0] + h[j][1]) + (h[j][2] + h[j][3]);
            }
            // butterfly across mod-8 lane classes
            #pragma unroll
            for (int j = 0; j < 4; ++j) {
                pj[j] += __shfl_xor_sync(0xFFFFFFFFu, pj[j], 8);
                pj[j] += __shfl_xor_sync(0xFFFFFFFFu, pj[j], 16);
            }
            // each 8-lane group reduces one j
            float v = (g == 0) ? pj[0] : (g == 1) ? pj[1] : (g == 2) ? pj[2] : pj[3];
            v += __shfl_xor_sync(0xFFFFFFFFu, v, 1);
            v += __shfl_xor_sync(0xFFFFFFFFu, v, 2);
            v += __shfl_xor_sync(0xFFFFFFFFu, v, 4);
            if ((ln & 7) == 0)
                sout[(size_t)(t0 + tl) * Hh] = v;
        }
        __syncthreads();
    }

    size_t base = ((size_t)(b * CH + k) * Nn + ln * 4) * Hh + cg * 32 + w * 4;
    #pragma unroll
    for (int i = 0; i < 4; ++i) {
        float4 v; v.x = h[0][i]; v.y = h[1][i]; v.z = h[2][i]; v.w = h[3][i];
        *(float4*)&g_hE[base + (size_t)i * Hh] = v;
    }
}

// ---------------- Pass 2: inter-chunk state chain ----------------
__global__ __launch_bounds__(256) void chain_kernel(const float* __restrict__ A_log)
{
    int g = blockIdx.x * 256 + threadIdx.x;        // 0 .. 65535
    int c = g & 127, n = (g >> 7) & 127, b = g >> 14;
    float Ac2 = -__expf(A_log[c]) * 1.44269504f;
    const float* cd = g_cumd + (size_t)b * Ll * Nn + n;
    float h = 0.f;
    #pragma unroll
    for (int k = 0; k < CH; ++k) {
        size_t idx = ((size_t)(b * CH + k) * Nn + n) * Hh + c;
        g_h0[idx] = h;
        float dec = ex2f(Ac2 * cd[(size_t)(k * CS + CS - 1) * Nn]);
        h = fmaf(dec, h, g_hE[idx]);
    }
}

// ---------------- Pass 3: fixup + combine ----------------
#define T3 8
__global__ __launch_bounds__(256) void fixup_kernel(
    const float* __restrict__ A_log, const float* __restrict__ Dv,
    const float* __restrict__ u)
{
    __shared__ __align__(16) float smh[32][128];
    __shared__ __align__(16) float smc[T3][128];

    int b = blockIdx.z, k = blockIdx.y, tg = blockIdx.x;
    int t0 = k * CS + tg * T3;
    int tid = threadIdx.x;
    int c = tid & 127, th = tid >> 7;

    float acc[4] = {0.f, 0.f, 0.f, 0.f};

    if (k > 0) {
        float Ac2 = -__expf(A_log[c]) * 1.44269504f;
        #pragma unroll
        for (int i = 0; i < 4; ++i) {
            int idx = tid + i * 256;
            int tt = idx >> 7, n = idx & 127;
            smc[tt][n] = g_cumd[(size_t)b * Ll * Nn + (size_t)(t0 + tt) * Nn + n];
        }
        const float4* h0p = (const float4*)(g_h0 + ((size_t)(b * CH + k) * Nn) * Hh);
        #pragma unroll
        for (int nb = 0; nb < 4; ++nb) {
            __syncthreads();
            #pragma unroll
            for (int i = 0; i < 4; ++i) {
                int idx = tid + i * 256;
                ((float4*)smh)[idx] = h0p[nb * 1024 + idx];
            }
            __syncthreads();
            #pragma unroll
            for (int n = 0; n < 32; ++n) {
                float hv = smh[n][c];
                #pragma unroll
                for (int j = 0; j < 4; ++j) {
                    float dl = smc[th * 4 + j][nb * 32 + n];
                    acc[j] = fmaf(ex2f(dl * Ac2), hv, acc[j]);
                }
            }
        }
    }

    #pragma unroll
    for (int j = 0; j < 4; ++j) {
        int t = t0 + th * 4 + j;
        size_t off = (size_t)b * Ll * Hh + (size_t)t * Hh + c;
        float S = g_S[off] + acc[j];
        float y = fmaf(S, g_C[off], Dv[c] * u[off]);
        g_y[off] = y * g_zs[off];
    }
}

// ---------------- launch ----------------
extern "C" void kernel_launch(void* const* d_in, const int* in_sizes, int n_in,
                              void* d_out, int out_size)
{
    const float* u      = (const float*)d_in[0];
    const float* W_in   = (const float*)d_in[1];
    const float* b_in   = (const float*)d_in[2];
    const float* conv_w = (const float*)d_in[3];
    const float* conv_b = (const float*)d_in[4];
    const float* W_x    = (const float*)d_in[5];
    const float* b_x    = (const float*)d_in[6];
    const float* A_log  = (const float*)d_in[7];
    const float* Dv     = (const float*)d_in[8];
    const float* W_out  = (const float*)d_in[9];
    const float* b_out  = (const float*)d_in[10];
    float* out = (float*)d_out;

    dim3 blk(256);
    gemm_kernel<1><<<dim3(ML / 64, 256 / 64), blk>>>(u, W_in, b_in, nullptr, 256);
    conv_kernel<<<(Bb * Ll * Ee + 255) / 256, blk>>>(conv_w, conv_b);
    gemm_kernel<2><<<dim3(ML / 64, 384 / 64), blk>>>(nullptr, W_x, b_x, nullptr, 384);
    scan_local_kernel<<<dim3(4, CH, Bb), blk>>>(A_log);
    chain_kernel<<<dim3(Bb * Nn * Hh / 256), blk>>>(A_log);
    fixup_kernel<<<dim3(CS / T3, CH, Bb), blk>>>(A_log, Dv, u);
    gemm_kernel<3><<<dim3(ML / 64, 128 / 64), blk>>>(nullptr, W_out, b_out, out, 128);
}

// round 12
// speedup vs baseline: 1.0177x; 1.0177x over previous
#include <cuda_runtime.h>

#define Bb 4
#define Ll 1024
#define Hh 128
#define Ee 128
#define Nn 128
#define ML (Bb*Ll)   // 4096
#define CH 32        // number of L-chunks
#define CS 32        // chunk size (CH*CS == Ll)

// ---------------- scratch (device globals: no allocations allowed) ----------------
__device__ float g_x[Bb*Ll*Ee];      // pre-conv x
__device__ float g_zs[Bb*Ll*Ee];     // silu(z)
__device__ float g_delta[Bb*Ll*Nn];  // softplus'd
__device__ float g_Braw[Bb*Ll*Nn];
__device__ float g_C[Bb*Ll*Hh];
__device__ float g_y[Bb*Ll*Hh];      // gated scan output (input to GEMM3)
__device__ float g_S[Bb*Ll*Hh];      // local (then full) n-sums
__device__ float g_cumd[Bb*Ll*Nn];   // within-chunk inclusive cumsum of delta
__device__ float g_hE[Bb*CH*Nn*Hh]; // chunk-end local states [b][k][n][c]
__device__ float g_h0[Bb*CH*Nn*Hh]; // chunk-start true states [b][k][n][c]

__device__ __forceinline__ float silu_(float x){ return x / (1.f + __expf(-x)); }
__device__ __forceinline__ float softplus_(float x){ return x > 20.f ? x : log1pf(__expf(x)); }
__device__ __forceinline__ float ex2f(float x){ float r; asm("ex2.approx.ftz.f32 %0, %1;" : "=f"(r) : "f"(x)); return r; }

// conv3+bias+silu on a float4 of channels (e0..e0+3) at time t of batch-row `row`.
__device__ __forceinline__ float4 conv4_(int row, int t, int e0,
    const float* __restrict__ w0, const float* __restrict__ w1,
    const float* __restrict__ w2, const float* __restrict__ cb)
{
    const float* xp = g_x + (size_t)row * 128 + e0;
    float4 xm = *(const float4*)xp;
    float4 xl = make_float4(0.f, 0.f, 0.f, 0.f);
    float4 xr = make_float4(0.f, 0.f, 0.f, 0.f);
    if (t > 0)         xl = *(const float4*)(xp - 128);
    if (t < Ll - 1)    xr = *(const float4*)(xp + 128);
    float4 v;
    v.x = silu_(fmaf(w0[0], xl.x, fmaf(w1[0], xm.x, fmaf(w2[0], xr.x, cb[0]))));
    v.y = silu_(fmaf(w0[1], xl.y, fmaf(w1[1], xm.y, fmaf(w2[1], xr.y, cb[1]))));
    v.z = silu_(fmaf(w0[2], xl.z, fmaf(w1[2], xm.z, fmaf(w2[2], xr.z, cb[2]))));
    v.w = silu_(fmaf(w0[3], xl.w, fmaf(w1[3], xm.w, fmaf(w2[3], xr.w, cb[3]))));
    return v;
}

// ---------------- 64x64-tile SGEMM, K=128, fused epilogues (R4 core) ---------------
// EPI=1: A=u -> g_x / g_zs(silu).  EPI=2: A=conv3(g_x) computed at stage time
// -> delta(softplus)/Braw/C.  EPI=3: A=g_y -> Cout.
template<int EPI>
__global__ __launch_bounds__(256) void gemm_kernel(
    const float* __restrict__ Ain, const float* __restrict__ Wp,
    const float* __restrict__ bias, float* __restrict__ Cout, int ldN,
    const float* __restrict__ cw, const float* __restrict__ cb)
{
    __shared__ __align__(16) float As[64][68];   // [row][k]
    __shared__ __align__(16) float Bs[64][64];   // [k][col]
    __shared__ float smw0[128], smw1[128], smw2[128], smcb[128];
    const float* Ap = (EPI == 1) ? Ain : g_y;

    int tid = threadIdx.x;
    int ty = tid >> 4, tx = tid & 15;
    int row0 = blockIdx.x * 64;
    int col0 = blockIdx.y * 64;

    if (EPI == 2) {
        if (tid < 128) {
            smw0[tid] = cw[tid * 3 + 0];
            smw1[tid] = cw[tid * 3 + 1];
            smw2[tid] = cw[tid * 3 + 2];
            smcb[tid] = cb[tid];
        }
        __syncthreads();
    }

    float acc[4][4];
    #pragma unroll
    for (int i = 0; i < 4; i++)
        #pragma unroll
        for (int j = 0; j < 4; j++) acc[i][j] = 0.f;

    #pragma unroll
    for (int kb = 0; kb < 2; ++kb) {
        #pragma unroll
        for (int i = 0; i < 4; ++i) {
            int f = tid + i * 256;
            int r = f >> 4, kq = f & 15;
            float4 v;
            if (EPI == 2) {
                int row = row0 + r;
                int e0 = kb * 64 + kq * 4;
                v = conv4_(row, row & (Ll - 1), e0,
                           smw0 + e0, smw1 + e0, smw2 + e0, smcb + e0);
            } else {
                v = *(const float4*)&Ap[(size_t)(row0 + r) * 128 + kb * 64 + kq * 4];
            }
            *(float4*)&As[r][kq * 4] = v;
        }
        #pragma unroll
        for (int i = 0; i < 4; ++i) {
            int f = tid + i * 256;
            int k = f >> 4, nq = f & 15;
            float4 v = *(const float4*)&Wp[(size_t)(kb * 64 + k) * ldN + col0 + nq * 4];
            *(float4*)&Bs[k][nq * 4] = v;
        }
        __syncthreads();
        #pragma unroll 16
        for (int k = 0; k < 64; ++k) {
            float4 bv = *(float4*)&Bs[k][tx * 4];
            float a0 = As[ty * 4 + 0][k];
            float a1 = As[ty * 4 + 1][k];
            float a2 = As[ty * 4 + 2][k];
            float a3 = As[ty * 4 + 3][k];
            acc[0][0] = fmaf(a0, bv.x, acc[0][0]); acc[0][1] = fmaf(a0, bv.y, acc[0][1]);
            acc[0][2] = fmaf(a0, bv.z, acc[0][2]); acc[0][3] = fmaf(a0, bv.w, acc[0][3]);
            acc[1][0] = fmaf(a1, bv.x, acc[1][0]); acc[1][1] = fmaf(a1, bv.y, acc[1][1]);
            acc[1][2] = fmaf(a1, bv.z, acc[1][2]); acc[1][3] = fmaf(a1, bv.w, acc[1][3]);
            acc[2][0] = fmaf(a2, bv.x, acc[2][0]); acc[2][1] = fmaf(a2, bv.y, acc[2][1]);
            acc[2][2] = fmaf(a2, bv.z, acc[2][2]); acc[2][3] = fmaf(a2, bv.w, acc[2][3]);
            acc[3][0] = fmaf(a3, bv.x, acc[3][0]); acc[3][1] = fmaf(a3, bv.y, acc[3][1]);
            acc[3][2] = fmaf(a3, bv.z, acc[3][2]); acc[3][3] = fmaf(a3, bv.w, acc[3][3]);
        }
        __syncthreads();
    }

    #pragma unroll
    for (int i = 0; i < 4; ++i) {
        int row = row0 + ty * 4 + i;
        #pragma unroll
        for (int j = 0; j < 4; ++j) {
            int col = col0 + tx * 4 + j;
            float v = acc[i][j] + bias[col];
            if (EPI == 1) {
                if (col < 128) g_x[(size_t)row * 128 + col] = v;
                else           g_zs[(size_t)row * 128 + col - 128] = silu_(v);
            } else if (EPI == 2) {
                if (col < 128)      g_delta[(size_t)row * 128 + col] = softplus_(v);
                else if (col < 256) g_Braw[(size_t)row * 128 + col - 128] = v;
                else                g_C[(size_t)row * 128 + col - 256] = v;
            } else {
                Cout[(size_t)row * 128 + col] = v;
            }
        }
    }
}

// ---------------- Pass 1: per-chunk local scan (4n x 4c states per thread) ----------
// x staged via inline conv3 from g_x (conv kernel eliminated).
__global__ __launch_bounds__(256) void scan_local_kernel(
    const float* __restrict__ A_log,
    const float* __restrict__ cw, const float* __restrict__ cb)
{
    __shared__ __align__(16) float smd[16][128];
    __shared__ __align__(16) float smb[16][128];
    __shared__ __align__(16) float smx[16][32];
    __shared__ float smP[4][32][33];
    __shared__ float sw0[32], sw1[32], sw2[32], scb[32];

    int b  = blockIdx.z;
    int k  = blockIdx.y;
    int cg = blockIdx.x;
    int tid = threadIdx.x;
    int w = tid >> 5, ln = tid & 31;

    if (tid < 32) {
        int e = cg * 32 + tid;
        sw0[tid] = cw[e * 3 + 0];
        sw1[tid] = cw[e * 3 + 1];
        sw2[tid] = cw[e * 3 + 2];
        scb[tid] = cb[e];
    }

    float Ac2[4];
    #pragma unroll
    for (int j = 0; j < 4; ++j)
        Ac2[j] = -__expf(A_log[cg * 32 + w * 4 + j]) * 1.44269504f;

    const float4* del4 = (const float4*)(g_delta + (size_t)b * Ll * Nn);
    const float4* br4  = (const float4*)(g_Braw  + (size_t)b * Ll * Nn);

    float h[4][4];
    #pragma unroll
    for (int j = 0; j < 4; ++j)
        #pragma unroll
        for (int i = 0; i < 4; ++i) h[j][i] = 0.f;

    float dc = 0.f;
    bool do_cum = (cg == 0) && (tid < 128);
    __syncthreads();   // weights visible before first staging

    for (int t0 = k * CS; t0 < (k + 1) * CS; t0 += 16) {
        #pragma unroll
        for (int i = 0; i < 2; ++i) {
            int idx = tid + i * 256;
            float4 d = del4[t0 * 32 + idx];
            float4 r = br4[t0 * 32 + idx];
            ((float4*)smd)[idx] = d;
            float4 p; p.x = d.x * r.x; p.y = d.y * r.y; p.z = d.z * r.z; p.w = d.w * r.w;
            ((float4*)smb)[idx] = p;
        }
        if (tid < 128) {
            int tt = tid >> 3, q = tid & 7;
            int t = t0 + tt;
            int e0 = cg * 32 + q * 4;
            float4 v = conv4_(b * Ll + t, t, e0,
                              sw0 + q * 4, sw1 + q * 4, sw2 + q * 4, scb + q * 4);
            *(float4*)&smx[tt][q * 4] = v;
        }
        __syncthreads();

        if (do_cum) {
            float* gout = g_cumd + (size_t)b * Ll * Nn + (size_t)t0 * Nn + tid;
            #pragma unroll
            for (int tl = 0; tl < 16; ++tl) { dc += smd[tl][tid]; gout[tl * 128] = dc; }
        }

        #pragma unroll
        for (int tb = 0; tb < 16; tb += 4) {
            #pragma unroll
            for (int tt = 0; tt < 4; ++tt) {
                int t = tb + tt;
                float4 d4 = *(float4*)&smd[t][ln * 4];
                float4 b4 = *(float4*)&smb[t][ln * 4];
                float4 x4 = *(float4*)&smx[t][w * 4];
                float dn[4] = {d4.x, d4.y, d4.z, d4.w};
                float bn[4] = {b4.x, b4.y, b4.z, b4.w};
                float xs[4] = {x4.x, x4.y, x4.z, x4.w};
                #pragma unroll
                for (int j = 0; j < 4; ++j) {
                    #pragma unroll
                    for (int i = 0; i < 4; ++i) {
                        float e = ex2f(dn[i] * Ac2[j]);
                        h[j][i] = fmaf(e, h[j][i], bn[i] * xs[j]);
                    }
                    smP[tt][ln][w * 4 + j] = (h[j][0] + h[j][1]) + (h[j][2] + h[j][3]);
                }
            }
            __syncthreads();
            if (tid < 128) {
                int tt = tid >> 5, c = tid & 31;
                float s = 0.f;
                #pragma unroll
                for (int q = 0; q < 32; ++q) s += smP[tt][q][c];
                int t = t0 + tb + tt;
                g_S[(size_t)b * Ll * Hh + (size_t)t * Hh + cg * 32 + c] = s;
            }
            __syncthreads();
        }
    }

    size_t base = ((size_t)(b * CH + k) * Nn + ln * 4) * Hh + cg * 32 + w * 4;
    #pragma unroll
    for (int i = 0; i < 4; ++i) {
        float4 v; v.x = h[0][i]; v.y = h[1][i]; v.z = h[2][i]; v.w = h[3][i];
        *(float4*)&g_hE[base + (size_t)i * Hh] = v;
    }
}

// ---------------- Pass 2: inter-chunk state chain ----------------
__global__ __launch_bounds__(256) void chain_kernel(const float* __restrict__ A_log)
{
    int g = blockIdx.x * 256 + threadIdx.x;        // 0 .. 65535
    int c = g & 127, n = (g >> 7) & 127, b = g >> 14;
    float Ac2 = -__expf(A_log[c]) * 1.44269504f;
    const float* cd = g_cumd + (size_t)b * Ll * Nn + n;
    float h = 0.f;
    #pragma unroll
    for (int k = 0; k < CH; ++k) {
        size_t idx = ((size_t)(b * CH + k) * Nn + n) * Hh + c;
        g_h0[idx] = h;
        float dec = ex2f(Ac2 * cd[(size_t)(k * CS + CS - 1) * Nn]);
        h = fmaf(dec, h, g_hE[idx]);
    }
}

// ---------------- Pass 3: fixup + combine ----------------
#define T3 8
__global__ __launch_bounds__(256) void fixup_kernel(
    const float* __restrict__ A_log, const float* __restrict__ Dv,
    const float* __restrict__ u)
{
    __shared__ __align__(16) float smh[32][128];
    __shared__ __align__(16) float smc[T3][128];

    int b = blockIdx.z, k = blockIdx.y, tg = blockIdx.x;
    int t0 = k * CS + tg * T3;
    int tid = threadIdx.x;
    int c = tid & 127, th = tid >> 7;

    float acc[4] = {0.f, 0.f, 0.f, 0.f};

    if (k > 0) {
        float Ac2 = -__expf(A_log[c]) * 1.44269504f;
        #pragma unroll
        for (int i = 0; i < 4; ++i) {
            int idx = tid + i * 256;
            int tt = idx >> 7, n = idx & 127;
            smc[tt][n] = g_cumd[(size_t)b * Ll * Nn + (size_t)(t0 + tt) * Nn + n];
        }
        const float4* h0p = (const float4*)(g_h0 + ((size_t)(b * CH + k) * Nn) * Hh);
        #pragma unroll
        for (int nb = 0; nb < 4; ++nb) {
            __syncthreads();
            #pragma unroll
            for (int i = 0; i < 4; ++i) {
                int idx = tid + i * 256;
                ((float4*)smh)[idx] = h0p[nb * 1024 + idx];
            }
            __syncthreads();
            #pragma unroll
            for (int n = 0; n < 32; ++n) {
                float hv = smh[n][c];
                #pragma unroll
                for (int j = 0; j < 4; ++j) {
                    float dl = smc[th * 4 + j][nb * 32 + n];
                    acc[j] = fmaf(ex2f(dl * Ac2), hv, acc[j]);
                }
            }
        }
    }

    #pragma unroll
    for (int j = 0; j < 4; ++j) {
        int t = t0 + th * 4 + j;
        size_t off = (size_t)b * Ll * Hh + (size_t)t * Hh + c;
        float S = g_S[off] + acc[j];
        float y = fmaf(S, g_C[off], Dv[c] * u[off]);
        g_y[off] = y * g_zs[off];
    }
}

// ---------------- launch ----------------
extern "C" void kernel_launch(void* const* d_in, const int* in_sizes, int n_in,
                              void* d_out, int out_size)
{
    const float* u      = (const float*)d_in[0];
    const float* W_in   = (const float*)d_in[1];
    const float* b_in   = (const float*)d_in[2];
    const float* conv_w = (const float*)d_in[3];
    const float* conv_b = (const float*)d_in[4];
    const float* W_x    = (const float*)d_in[5];
    const float* b_x    = (const float*)d_in[6];
    const float* A_log  = (const float*)d_in[7];
    const float* Dv     = (const float*)d_in[8];
    const float* W_out  = (const float*)d_in[9];
    const float* b_out  = (const float*)d_in[10];
    float* out = (float*)d_out;

    dim3 blk(256);
    gemm_kernel<1><<<dim3(ML / 64, 256 / 64), blk>>>(u, W_in, b_in, nullptr, 256, nullptr, nullptr);
    gemm_kernel<2><<<dim3(ML / 64, 384 / 64), blk>>>(nullptr, W_x, b_x, nullptr, 384, conv_w, conv_b);
    scan_local_kernel<<<dim3(4, CH, Bb), blk>>>(A_log, conv_w, conv_b);
    chain_kernel<<<dim3(Bb * Nn * Hh / 256), blk>>>(A_log);
    fixup_kernel<<<dim3(CS / T3, CH, Bb), blk>>>(A_log, Dv, u);
    gemm_kernel<3><<<dim3(ML / 64, 128 / 64), blk>>>(nullptr, W_out, b_out, out, 128, nullptr, nullptr);
}

// round 13
// speedup vs baseline: 1.1149x; 1.0956x over previous
#include <cuda_runtime.h>

#define Bb 4
#define Ll 1024
#define Hh 128
#define Ee 128
#define Nn 128
#define ML (Bb*Ll)   // 4096
#define CH 32        // number of L-chunks
#define CS 32        // chunk size (CH*CS == Ll)

// ---------------- scratch (device globals: no allocations allowed) ----------------
__device__ float g_x[Bb*Ll*Ee];      // pre-conv x
__device__ float g_zs[Bb*Ll*Ee];     // silu(z)
__device__ float g_xc[Bb*Ll*Ee];     // post-conv silu(x)
__device__ float g_delta[Bb*Ll*Nn];  // softplus'd
__device__ float g_Braw[Bb*Ll*Nn];
__device__ float g_C[Bb*Ll*Hh];
__device__ float g_y[Bb*Ll*Hh];      // gated scan output (input to GEMM3)
__device__ float g_S[Bb*Ll*Hh];      // local (then full) n-sums
__device__ float g_cumd[Bb*Ll*Nn];   // within-chunk inclusive cumsum of delta
__device__ float g_hE[Bb*CH*Nn*Hh];  // chunk-end local states [b][k][n][c]
__device__ float g_h0[Bb*CH*Nn*Hh];  // chunk-start true states [b][k][n][c]

__device__ __forceinline__ float silu_(float x){ return x / (1.f + __expf(-x)); }
__device__ __forceinline__ float softplus_(float x){ return x > 20.f ? x : log1pf(__expf(x)); }
__device__ __forceinline__ float ex2f(float x){ float r; asm("ex2.approx.ftz.f32 %0, %1;" : "=f"(r) : "f"(x)); return r; }

// ---------------- generic 64x64-tile SGEMM, K=128, fused epilogues (R4-exact) ------
template<int EPI>
__global__ __launch_bounds__(256) void gemm_kernel(
    const float* __restrict__ Ain, const float* __restrict__ Wp,
    const float* __restrict__ bias, float* __restrict__ Cout, int ldN)
{
    __shared__ __align__(16) float As[64][68];   // [row][k]
    __shared__ __align__(16) float Bs[64][64];   // [k][col]
    const float* Ap = (EPI == 1) ? Ain : (EPI == 2 ? g_xc : g_y);

    int tid = threadIdx.x;
    int ty = tid >> 4, tx = tid & 15;
    int row0 = blockIdx.x * 64;
    int col0 = blockIdx.y * 64;

    float acc[4][4];
    #pragma unroll
    for (int i = 0; i < 4; i++)
        #pragma unroll
        for (int j = 0; j < 4; j++) acc[i][j] = 0.f;

    #pragma unroll
    for (int kb = 0; kb < 2; ++kb) {
        #pragma unroll
        for (int i = 0; i < 4; ++i) {
            int f = tid + i * 256;
            int r = f >> 4, kq = f & 15;
            float4 v = *(const float4*)&Ap[(size_t)(row0 + r) * 128 + kb * 64 + kq * 4];
            *(float4*)&As[r][kq * 4] = v;
        }
        #pragma unroll
        for (int i = 0; i < 4; ++i) {
            int f = tid + i * 256;
            int k = f >> 4, nq = f & 15;
            float4 v = *(const float4*)&Wp[(size_t)(kb * 64 + k) * ldN + col0 + nq * 4];
            *(float4*)&Bs[k][nq * 4] = v;
        }
        __syncthreads();
        #pragma unroll 16
        for (int k = 0; k < 64; ++k) {
            float4 bv = *(float4*)&Bs[k][tx * 4];
            float a0 = As[ty * 4 + 0][k];
            float a1 = As[ty * 4 + 1][k];
            float a2 = As[ty * 4 + 2][k];
            float a3 = As[ty * 4 + 3][k];
            acc[0][0] = fmaf(a0, bv.x, acc[0][0]); acc[0][1] = fmaf(a0, bv.y, acc[0][1]);
            acc[0][2] = fmaf(a0, bv.z, acc[0][2]); acc[0][3] = fmaf(a0, bv.w, acc[0][3]);
            acc[1][0] = fmaf(a1, bv.x, acc[1][0]); acc[1][1] = fmaf(a1, bv.y, acc[1][1]);
            acc[1][2] = fmaf(a1, bv.z, acc[1][2]); acc[1][3] = fmaf(a1, bv.w, acc[1][3]);
            acc[2][0] = fmaf(a2, bv.x, acc[2][0]); acc[2][1] = fmaf(a2, bv.y, acc[2][1]);
            acc[2][2] = fmaf(a2, bv.z, acc[2][2]); acc[2][3] = fmaf(a2, bv.w, acc[2][3]);
            acc[3][0] = fmaf(a3, bv.x, acc[3][0]); acc[3][1] = fmaf(a3, bv.y, acc[3][1]);
            acc[3][2] = fmaf(a3, bv.z, acc[3][2]); acc[3][3] = fmaf(a3, bv.w, acc[3][3]);
        }
        __syncthreads();
    }

    #pragma unroll
    for (int i = 0; i < 4; ++i) {
        int row = row0 + ty * 4 + i;
        #pragma unroll
        for (int j = 0; j < 4; ++j) {
            int col = col0 + tx * 4 + j;
            float v = acc[i][j] + bias[col];
            if (EPI == 1) {
                if (col < 128) g_x[(size_t)row * 128 + col] = v;
                else           g_zs[(size_t)row * 128 + col - 128] = silu_(v);
            } else if (EPI == 2) {
                if (col < 128)      g_delta[(size_t)row * 128 + col] = softplus_(v);
                else if (col < 256) g_Braw[(size_t)row * 128 + col - 128] = v;
                else                g_C[(size_t)row * 128 + col - 256] = v;
            } else {
                Cout[(size_t)row * 128 + col] = v;
            }
        }
    }
}

// ---------------- depthwise conv3 (+bias, silu) ----------------
__global__ void conv_kernel(const float* __restrict__ cw, const float* __restrict__ cb)
{
    int idx = blockIdx.x * blockDim.x + threadIdx.x;
    if (idx >= Bb * Ll * Ee) return;
    int e = idx & 127;
    int t = (idx >> 7) & (Ll - 1);
    float w0 = cw[e * 3 + 0], w1 = cw[e * 3 + 1], w2 = cw[e * 3 + 2];
    float xm = g_x[idx];
    float xl = (t > 0)      ? g_x[idx - 128] : 0.f;
    float xr = (t < Ll - 1) ? g_x[idx + 128] : 0.f;
    float v = fmaf(w0, xl, fmaf(w1, xm, fmaf(w2, xr, cb[e])));
    g_xc[idx] = silu_(v);
}

// ---------------- Pass 1: per-chunk local scan (4n x 4c states per thread) ----------
__global__ __launch_bounds__(256) void scan_local_kernel(const float* __restrict__ A_log)
{
    __shared__ __align__(16) float smd[16][128];
    __shared__ __align__(16) float smb[16][128];
    __shared__ __align__(16) float smx[16][32];
    __shared__ float smP[4][32][33];

    int b  = blockIdx.z;
    int k  = blockIdx.y;
    int cg = blockIdx.x;
    int tid = threadIdx.x;
    int w = tid >> 5, ln = tid & 31;

    float Ac2[4];
    #pragma unroll
    for (int j = 0; j < 4; ++j)
        Ac2[j] = -__expf(A_log[cg * 32 + w * 4 + j]) * 1.44269504f;

    const float4* del4 = (const float4*)(g_delta + (size_t)b * Ll * Nn);
    const float4* br4  = (const float4*)(g_Braw  + (size_t)b * Ll * Nn);
    const float* xcb   = g_xc + (size_t)b * Ll * Ee + cg * 32;

    float h[4][4];
    #pragma unroll
    for (int j = 0; j < 4; ++j)
        #pragma unroll
        for (int i = 0; i < 4; ++i) h[j][i] = 0.f;

    float dc = 0.f;
    bool do_cum = (cg == 0) && (tid < 128);

    for (int t0 = k * CS; t0 < (k + 1) * CS; t0 += 16) {
        #pragma unroll
        for (int i = 0; i < 2; ++i) {
            int idx = tid + i * 256;
            float4 d = del4[t0 * 32 + idx];
            float4 r = br4[t0 * 32 + idx];
            ((float4*)smd)[idx] = d;
            float4 p; p.x = d.x * r.x; p.y = d.y * r.y; p.z = d.z * r.z; p.w = d.w * r.w;
            ((float4*)smb)[idx] = p;
        }
        if (tid < 128) {
            int tt = tid >> 3, q = tid & 7;
            *(float4*)&smx[tt][q * 4] = *(const float4*)&xcb[(size_t)(t0 + tt) * Ee + q * 4];
        }
        __syncthreads();

        if (do_cum) {
            float* gout = g_cumd + (size_t)b * Ll * Nn + (size_t)t0 * Nn + tid;
            #pragma unroll
            for (int tl = 0; tl < 16; ++tl) { dc += smd[tl][tid]; gout[tl * 128] = dc; }
        }

        #pragma unroll
        for (int tb = 0; tb < 16; tb += 4) {
            #pragma unroll
            for (int tt = 0; tt < 4; ++tt) {
                int t = tb + tt;
                float4 d4 = *(float4*)&smd[t][ln * 4];
                float4 b4 = *(float4*)&smb[t][ln * 4];
                float4 x4 = *(float4*)&smx[t][w * 4];
                float dn[4] = {d4.x, d4.y, d4.z, d4.w};
                float bn[4] = {b4.x, b4.y, b4.z, b4.w};
                float xs[4] = {x4.x, x4.y, x4.z, x4.w};
                #pragma unroll
                for (int j = 0; j < 4; ++j) {
                    #pragma unroll
                    for (int i = 0; i < 4; ++i) {
                        float e = ex2f(dn[i] * Ac2[j]);
                        h[j][i] = fmaf(e, h[j][i], bn[i] * xs[j]);
                    }
                    smP[tt][ln][w * 4 + j] = (h[j][0] + h[j][1]) + (h[j][2] + h[j][3]);
                }
            }
            __syncthreads();
            if (tid < 128) {
                int tt = tid >> 5, c = tid & 31;
                float s = 0.f;
                #pragma unroll
                for (int q = 0; q < 32; ++q) s += smP[tt][q][c];
                int t = t0 + tb + tt;
                g_S[(size_t)b * Ll * Hh + (size_t)t * Hh + cg * 32 + c] = s;
            }
            __syncthreads();
        }
    }

    size_t base = ((size_t)(b * CH + k) * Nn + ln * 4) * Hh + cg * 32 + w * 4;
    #pragma unroll
    for (int i = 0; i < 4; ++i) {
        float4 v; v.x = h[0][i]; v.y = h[1][i]; v.z = h[2][i]; v.w = h[3][i];
        *(float4*)&g_hE[base + (size_t)i * Hh] = v;
    }
}

// ---------------- Pass 2: inter-chunk state chain (batched-latency version) --------
// All 64 load addresses are static: batch-load cd[32] + hE[32] (one latency wave),
// precompute decays, then run the register-only serial fma chain + stores.
__global__ __launch_bounds__(256) void chain_kernel(const float* __restrict__ A_log)
{
    int g = blockIdx.x * 256 + threadIdx.x;        // 0 .. 65535
    int c = g & 127, n = (g >> 7) & 127, b = g >> 14;
    float Ac2 = -__expf(A_log[c]) * 1.44269504f;
    const float* cd = g_cumd + (size_t)b * Ll * Nn + n;
    size_t base = ((size_t)(b * CH) * Nn + n) * Hh + c;   // k stride = Nn*Hh

    float dec[CH], hE[CH];
    #pragma unroll
    for (int k = 0; k < CH; ++k)
        dec[k] = cd[(size_t)(k * CS + CS - 1) * Nn];
    #pragma unroll
    for (int k = 0; k < CH; ++k)
        hE[k] = g_hE[base + (size_t)k * (Nn * Hh)];
    #pragma unroll
    for (int k = 0; k < CH; ++k)
        dec[k] = ex2f(Ac2 * dec[k]);

    float h = 0.f;
    #pragma unroll
    for (int k = 0; k < CH; ++k) {
        g_h0[base + (size_t)k * (Nn * Hh)] = h;
        h = fmaf(dec[k], h, hE[k]);
    }
}

// ---------------- Pass 3: fixup + combine ----------------
#define T3 8
__global__ __launch_bounds__(256) void fixup_kernel(
    const float* __restrict__ A_log, const float* __restrict__ Dv,
    const float* __restrict__ u)
{
    __shared__ __align__(16) float smh[32][128];
    __shared__ __align__(16) float smc[T3][128];

    int b = blockIdx.z, k = blockIdx.y, tg = blockIdx.x;
    int t0 = k * CS + tg * T3;
    int tid = threadIdx.x;
    int c = tid & 127, th = tid >> 7;

    float acc[4] = {0.f, 0.f, 0.f, 0.f};

    if (k > 0) {
        float Ac2 = -__expf(A_log[c]) * 1.44269504f;
        #pragma unroll
        for (int i = 0; i < 4; ++i) {
            int idx = tid + i * 256;
            int tt = idx >> 7, n = idx & 127;
            smc[tt][n] = g_cumd[(size_t)b * Ll * Nn + (size_t)(t0 + tt) * Nn + n];
        }
        const float4* h0p = (const float4*)(g_h0 + ((size_t)(b * CH + k) * Nn) * Hh);
        #pragma unroll
        for (int nb = 0; nb < 4; ++nb) {
            __syncthreads();
            #pragma unroll
            for (int i = 0; i < 4; ++i) {
                int idx = tid + i * 256;
                ((float4*)smh)[idx] = h0p[nb * 1024 + idx];
            }
            __syncthreads();
            #pragma unroll
            for (int n = 0; n < 32; ++n) {
                float hv = smh[n][c];
                #pragma unroll
                for (int j = 0; j < 4; ++j) {
                    float dl = smc[th * 4 + j][nb * 32 + n];
                    acc[j] = fmaf(ex2f(dl * Ac2), hv, acc[j]);
                }
            }
        }
    }

    #pragma unroll
    for (int j = 0; j < 4; ++j) {
        int t = t0 + th * 4 + j;
        size_t off = (size_t)b * Ll * Hh + (size_t)t * Hh + c;
        float S = g_S[off] + acc[j];
        float y = fmaf(S, g_C[off], Dv[c] * u[off]);
        g_y[off] = y * g_zs[off];
    }
}

// ---------------- launch ----------------
extern "C" void kernel_launch(void* const* d_in, const int* in_sizes, int n_in,
                              void* d_out, int out_size)
{
    const float* u      = (const float*)d_in[0];
    const float* W_in   = (const float*)d_in[1];
    const float* b_in   = (const float*)d_in[2];
    const float* conv_w = (const float*)d_in[3];
    const float* conv_b = (const float*)d_in[4];
    const float* W_x    = (const float*)d_in[5];
    const float* b_x    = (const float*)d_in[6];
    const float* A_log  = (const float*)d_in[7];
    const float* Dv     = (const float*)d_in[8];
    const float* W_out  = (const float*)d_in[9];
    const float* b_out  = (const float*)d_in[10];
    float* out = (float*)d_out;

    dim3 blk(256);
    gemm_kernel<1><<<dim3(ML / 64, 256 / 64), blk>>>(u, W_in, b_in, nullptr, 256);
    conv_kernel<<<(Bb * Ll * Ee + 255) / 256, blk>>>(conv_w, conv_b);
    gemm_kernel<2><<<dim3(ML / 64, 384 / 64), blk>>>(nullptr, W_x, b_x, nullptr, 384);
    scan_local_kernel<<<dim3(4, CH, Bb), blk>>>(A_log);
    chain_kernel<<<dim3(Bb * Nn * Hh / 256), blk>>>(A_log);
    fixup_kernel<<<dim3(CS / T3, CH, Bb), blk>>>(A_log, Dv, u);
    gemm_kernel<3><<<dim3(ML / 64, 128 / 64), blk>>>(nullptr, W_out, b_out, out, 128);
}

// round 14
// speedup vs baseline: 1.1154x; 1.0004x over previous
#include <cuda_runtime.h>

#define Bb 4
#define Ll 1024
#define Hh 128
#define Ee 128
#define Nn 128
#define ML (Bb*Ll)   // 4096
#define CH 64        // number of L-chunks
#define CS 16        // chunk size (CH*CS == Ll)
#define CG 16        // chain batch group size

// ---------------- scratch (device globals: no allocations allowed) ----------------
__device__ float g_x[Bb*Ll*Ee];      // pre-conv x
__device__ float g_zs[Bb*Ll*Ee];     // silu(z)
__device__ float g_xc[Bb*Ll*Ee];     // post-conv silu(x)
__device__ float g_delta[Bb*Ll*Nn];  // softplus'd
__device__ float g_Braw[Bb*Ll*Nn];
__device__ float g_C[Bb*Ll*Hh];
__device__ float g_y[Bb*Ll*Hh];      // gated scan output (input to GEMM3)
__device__ float g_S[Bb*Ll*Hh];      // local (then full) n-sums
__device__ float g_cumd[Bb*Ll*Nn];   // within-chunk inclusive cumsum of delta
__device__ float g_hE[Bb*CH*Nn*Hh]; // chunk-end local states [b][k][n][c]
__device__ float g_h0[Bb*CH*Nn*Hh]; // chunk-start true states [b][k][n][c]

__device__ __forceinline__ float silu_(float x){ return x / (1.f + __expf(-x)); }
__device__ __forceinline__ float softplus_(float x){ return x > 20.f ? x : log1pf(__expf(x)); }
__device__ __forceinline__ float ex2f(float x){ float r; asm("ex2.approx.ftz.f32 %0, %1;" : "=f"(r) : "f"(x)); return r; }

// ---------------- generic 64x64-tile SGEMM, K=128, fused epilogues (R4-exact) ------
template<int EPI>
__global__ __launch_bounds__(256) void gemm_kernel(
    const float* __restrict__ Ain, const float* __restrict__ Wp,
    const float* __restrict__ bias, float* __restrict__ Cout, int ldN)
{
    __shared__ __align__(16) float As[64][68];   // [row][k]
    __shared__ __align__(16) float Bs[64][64];   // [k][col]
    const float* Ap = (EPI == 1) ? Ain : (EPI == 2 ? g_xc : g_y);

    int tid = threadIdx.x;
    int ty = tid >> 4, tx = tid & 15;
    int row0 = blockIdx.x * 64;
    int col0 = blockIdx.y * 64;

    float acc[4][4];
    #pragma unroll
    for (int i = 0; i < 4; i++)
        #pragma unroll
        for (int j = 0; j < 4; j++) acc[i][j] = 0.f;

    #pragma unroll
    for (int kb = 0; kb < 2; ++kb) {
        #pragma unroll
        for (int i = 0; i < 4; ++i) {
            int f = tid + i * 256;
            int r = f >> 4, kq = f & 15;
            float4 v = *(const float4*)&Ap[(size_t)(row0 + r) * 128 + kb * 64 + kq * 4];
            *(float4*)&As[r][kq * 4] = v;
        }
        #pragma unroll
        for (int i = 0; i < 4; ++i) {
            int f = tid + i * 256;
            int k = f >> 4, nq = f & 15;
            float4 v = *(const float4*)&Wp[(size_t)(kb * 64 + k) * ldN + col0 + nq * 4];
            *(float4*)&Bs[k][nq * 4] = v;
        }
        __syncthreads();
        #pragma unroll 16
        for (int k = 0; k < 64; ++k) {
            float4 bv = *(float4*)&Bs[k][tx * 4];
            float a0 = As[ty * 4 + 0][k];
            float a1 = As[ty * 4 + 1][k];
            float a2 = As[ty * 4 + 2][k];
            float a3 = As[ty * 4 + 3][k];
            acc[0][0] = fmaf(a0, bv.x, acc[0][0]); acc[0][1] = fmaf(a0, bv.y, acc[0][1]);
            acc[0][2] = fmaf(a0, bv.z, acc[0][2]); acc[0][3] = fmaf(a0, bv.w, acc[0][3]);
            acc[1][0] = fmaf(a1, bv.x, acc[1][0]); acc[1][1] = fmaf(a1, bv.y, acc[1][1]);
            acc[1][2] = fmaf(a1, bv.z, acc[1][2]); acc[1][3] = fmaf(a1, bv.w, acc[1][3]);
            acc[2][0] = fmaf(a2, bv.x, acc[2][0]); acc[2][1] = fmaf(a2, bv.y, acc[2][1]);
            acc[2][2] = fmaf(a2, bv.z, acc[2][2]); acc[2][3] = fmaf(a2, bv.w, acc[2][3]);
            acc[3][0] = fmaf(a3, bv.x, acc[3][0]); acc[3][1] = fmaf(a3, bv.y, acc[3][1]);
            acc[3][2] = fmaf(a3, bv.z, acc[3][2]); acc[3][3] = fmaf(a3, bv.w, acc[3][3]);
        }
        __syncthreads();
    }

    #pragma unroll
    for (int i = 0; i < 4; ++i) {
        int row = row0 + ty * 4 + i;
        #pragma unroll
        for (int j = 0; j < 4; ++j) {
            int col = col0 + tx * 4 + j;
            float v = acc[i][j] + bias[col];
            if (EPI == 1) {
                if (col < 128) g_x[(size_t)row * 128 + col] = v;
                else           g_zs[(size_t)row * 128 + col - 128] = silu_(v);
            } else if (EPI == 2) {
                if (col < 128)      g_delta[(size_t)row * 128 + col] = softplus_(v);
                else if (col < 256) g_Braw[(size_t)row * 128 + col - 128] = v;
                else                g_C[(size_t)row * 128 + col - 256] = v;
            } else {
                Cout[(size_t)row * 128 + col] = v;
            }
        }
    }
}

// ---------------- depthwise conv3 (+bias, silu) ----------------
__global__ void conv_kernel(const float* __restrict__ cw, const float* __restrict__ cb)
{
    int idx = blockIdx.x * blockDim.x + threadIdx.x;
    if (idx >= Bb * Ll * Ee) return;
    int e = idx & 127;
    int t = (idx >> 7) & (Ll - 1);
    float w0 = cw[e * 3 + 0], w1 = cw[e * 3 + 1], w2 = cw[e * 3 + 2];
    float xm = g_x[idx];
    float xl = (t > 0)      ? g_x[idx - 128] : 0.f;
    float xr = (t < Ll - 1) ? g_x[idx + 128] : 0.f;
    float v = fmaf(w0, xl, fmaf(w1, xm, fmaf(w2, xr, cb[e])));
    g_xc[idx] = silu_(v);
}

// ---------------- Pass 1: per-chunk local scan (4n x 4c states per thread) ----------
// grid (4, CH, Bb); CS=16 -> one 16-t staging block per chunk (1024 blocks).
__global__ __launch_bounds__(256) void scan_local_kernel(const float* __restrict__ A_log)
{
    __shared__ __align__(16) float smd[16][128];
    __shared__ __align__(16) float smb[16][128];
    __shared__ __align__(16) float smx[16][32];
    __shared__ float smP[4][32][33];

    int b  = blockIdx.z;
    int k  = blockIdx.y;
    int cg = blockIdx.x;
    int tid = threadIdx.x;
    int w = tid >> 5, ln = tid & 31;

    float Ac2[4];
    #pragma unroll
    for (int j = 0; j < 4; ++j)
        Ac2[j] = -__expf(A_log[cg * 32 + w * 4 + j]) * 1.44269504f;

    const float4* del4 = (const float4*)(g_delta + (size_t)b * Ll * Nn);
    const float4* br4  = (const float4*)(g_Braw  + (size_t)b * Ll * Nn);
    const float* xcb   = g_xc + (size_t)b * Ll * Ee + cg * 32;

    float h[4][4];
    #pragma unroll
    for (int j = 0; j < 4; ++j)
        #pragma unroll
        for (int i = 0; i < 4; ++i) h[j][i] = 0.f;

    float dc = 0.f;
    bool do_cum = (cg == 0) && (tid < 128);

    for (int t0 = k * CS; t0 < (k + 1) * CS; t0 += 16) {
        #pragma unroll
        for (int i = 0; i < 2; ++i) {
            int idx = tid + i * 256;
            float4 d = del4[t0 * 32 + idx];
            float4 r = br4[t0 * 32 + idx];
            ((float4*)smd)[idx] = d;
            float4 p; p.x = d.x * r.x; p.y = d.y * r.y; p.z = d.z * r.z; p.w = d.w * r.w;
            ((float4*)smb)[idx] = p;
        }
        if (tid < 128) {
            int tt = tid >> 3, q = tid & 7;
            *(float4*)&smx[tt][q * 4] = *(const float4*)&xcb[(size_t)(t0 + tt) * Ee + q * 4];
        }
        __syncthreads();

        if (do_cum) {
            float* gout = g_cumd + (size_t)b * Ll * Nn + (size_t)t0 * Nn + tid;
            #pragma unroll
            for (int tl = 0; tl < 16; ++tl) { dc += smd[tl][tid]; gout[tl * 128] = dc; }
        }

        #pragma unroll
        for (int tb = 0; tb < 16; tb += 4) {
            #pragma unroll
            for (int tt = 0; tt < 4; ++tt) {
                int t = tb + tt;
                float4 d4 = *(float4*)&smd[t][ln * 4];
                float4 b4 = *(float4*)&smb[t][ln * 4];
                float4 x4 = *(float4*)&smx[t][w * 4];
                float dn[4] = {d4.x, d4.y, d4.z, d4.w};
                float bn[4] = {b4.x, b4.y, b4.z, b4.w};
                float xs[4] = {x4.x, x4.y, x4.z, x4.w};
                #pragma unroll
                for (int j = 0; j < 4; ++j) {
                    #pragma unroll
                    for (int i = 0; i < 4; ++i) {
                        float e = ex2f(dn[i] * Ac2[j]);
                        h[j][i] = fmaf(e, h[j][i], bn[i] * xs[j]);
                    }
                    smP[tt][ln][w * 4 + j] = (h[j][0] + h[j][1]) + (h[j][2] + h[j][3]);
                }
            }
            __syncthreads();
            if (tid < 128) {
                int tt = tid >> 5, c = tid & 31;
                float s = 0.f;
                #pragma unroll
                for (int q = 0; q < 32; ++q) s += smP[tt][q][c];
                int t = t0 + tb + tt;
                g_S[(size_t)b * Ll * Hh + (size_t)t * Hh + cg * 32 + c] = s;
            }
            __syncthreads();
        }
    }

    size_t base = ((size_t)(b * CH + k) * Nn + ln * 4) * Hh + cg * 32 + w * 4;
    #pragma unroll
    for (int i = 0; i < 4; ++i) {
        float4 v; v.x = h[0][i]; v.y = h[1][i]; v.z = h[2][i]; v.w = h[3][i];
        *(float4*)&g_hE[base + (size_t)i * Hh] = v;
    }
}

// ---------------- Pass 2: inter-chunk state chain (grouped batched loads) ----------
// CH=64 chunks chained in 4 groups of CG=16: per group, batch-load cd/hE (MLP=32),
// precompute decays, then extend the register-only serial fma chain.
__global__ __launch_bounds__(256) void chain_kernel(const float* __restrict__ A_log)
{
    int g = blockIdx.x * 256 + threadIdx.x;        // 0 .. 65535
    int c = g & 127, n = (g >> 7) & 127, b = g >> 14;
    float Ac2 = -__expf(A_log[c]) * 1.44269504f;
    const float* cd = g_cumd + (size_t)b * Ll * Nn + n;
    size_t base = ((size_t)(b * CH) * Nn + n) * Hh + c;   // k stride = Nn*Hh

    float h = 0.f;
    #pragma unroll
    for (int grp = 0; grp < CH / CG; ++grp) {
        int k0 = grp * CG;
        float dec[CG], hE[CG];
        #pragma unroll
        for (int k = 0; k < CG; ++k)
            dec[k] = cd[(size_t)((k0 + k) * CS + CS - 1) * Nn];
        #pragma unroll
        for (int k = 0; k < CG; ++k)
            hE[k] = g_hE[base + (size_t)(k0 + k) * (Nn * Hh)];
        #pragma unroll
        for (int k = 0; k < CG; ++k)
            dec[k] = ex2f(Ac2 * dec[k]);
        #pragma unroll
        for (int k = 0; k < CG; ++k) {
            g_h0[base + (size_t)(k0 + k) * (Nn * Hh)] = h;
            h = fmaf(dec[k], h, hE[k]);
        }
    }
}

// ---------------- Pass 3: fixup + combine ----------------
#define T3 8
__global__ __launch_bounds__(256) void fixup_kernel(
    const float* __restrict__ A_log, const float* __restrict__ Dv,
    const float* __restrict__ u)
{
    __shared__ __align__(16) float smh[32][128];
    __shared__ __align__(16) float smc[T3][128];

    int b = blockIdx.z, k = blockIdx.y, tg = blockIdx.x;
    int t0 = k * CS + tg * T3;
    int tid = threadIdx.x;
    int c = tid & 127, th = tid >> 7;

    float acc[4] = {0.f, 0.f, 0.f, 0.f};

    if (k > 0) {
        float Ac2 = -__expf(A_log[c]) * 1.44269504f;
        #pragma unroll
        for (int i = 0; i < 4; ++i) {
            int idx = tid + i * 256;
            int tt = idx >> 7, n = idx & 127;
            smc[tt][n] = g_cumd[(size_t)b * Ll * Nn + (size_t)(t0 + tt) * Nn + n];
        }
        const float4* h0p = (const float4*)(g_h0 + ((size_t)(b * CH + k) * Nn) * Hh);
        #pragma unroll
        for (int nb = 0; nb < 4; ++nb) {
            __syncthreads();
            #pragma unroll
            for (int i = 0; i < 4; ++i) {
                int idx = tid + i * 256;
                ((float4*)smh)[idx] = h0p[nb * 1024 + idx];
            }
            __syncthreads();
            #pragma unroll
            for (int n = 0; n < 32; ++n) {
                float hv = smh[n][c];
                #pragma unroll
                for (int j = 0; j < 4; ++j) {
                    float dl = smc[th * 4 + j][nb * 32 + n];
                    acc[j] = fmaf(ex2f(dl * Ac2), hv, acc[j]);
                }
            }
        }
    }

    #pragma unroll
    for (int j = 0; j < 4; ++j) {
        int t = t0 + th * 4 + j;
        size_t off = (size_t)b * Ll * Hh + (size_t)t * Hh + c;
        float S = g_S[off] + acc[j];
        float y = fmaf(S, g_C[off], Dv[c] * u[off]);
        g_y[off] = y * g_zs[off];
    }
}

// ---------------- launch ----------------
extern "C" void kernel_launch(void* const* d_in, const int* in_sizes, int n_in,
                              void* d_out, int out_size)
{
    const float* u      = (const float*)d_in[0];
    const float* W_in   = (const float*)d_in[1];
    const float* b_in   = (const float*)d_in[2];
    const float* conv_w = (const float*)d_in[3];
    const float* conv_b = (const float*)d_in[4];
    const float* W_x    = (const float*)d_in[5];
    const float* b_x    = (const float*)d_in[6];
    const float* A_log  = (const float*)d_in[7];
    const float* Dv     = (const float*)d_in[8];
    const float* W_out  = (const float*)d_in[9];
    const float* b_out  = (const float*)d_in[10];
    float* out = (float*)d_out;

    dim3 blk(256);
    gemm_kernel<1><<<dim3(ML / 64, 256 / 64), blk>>>(u, W_in, b_in, nullptr, 256);
    conv_kernel<<<(Bb * Ll * Ee + 255) / 256, blk>>>(conv_w, conv_b);
    gemm_kernel<2><<<dim3(ML / 64, 384 / 64), blk>>>(nullptr, W_x, b_x, nullptr, 384);
    scan_local_kernel<<<dim3(4, CH, Bb), blk>>>(A_log);
    chain_kernel<<<dim3(Bb * Nn * Hh / 256), blk>>>(A_log);
    fixup_kernel<<<dim3(CS / T3, CH, Bb), blk>>>(A_log, Dv, u);
    gemm_kernel<3><<<dim3(ML / 64, 128 / 64), blk>>>(nullptr, W_out, b_out, out, 128);
}

// round 16
// speedup vs baseline: 1.1474x; 1.0287x over previous
#include <cuda_runtime.h>

#define Bb 4
#define Ll 1024
#define Hh 128
#define Ee 128
#define Nn 128
#define ML (Bb*Ll)   // 4096
#define CH 64        // number of L-chunks
#define CS 16        // chunk size (CH*CS == Ll)
#define CG 16        // chain batch group size

// ---------------- scratch (device globals: no allocations allowed) ----------------
__device__ float g_x[Bb*Ll*Ee];      // pre-conv x
__device__ float g_zs[Bb*Ll*Ee];     // silu(z)
__device__ float g_xc[Bb*Ll*Ee];     // post-conv silu(x)
__device__ float g_delta[Bb*Ll*Nn];  // softplus'd
__device__ float g_Braw[Bb*Ll*Nn];
__device__ float g_C[Bb*Ll*Hh];
__device__ float g_y[Bb*Ll*Hh];      // gated scan output (input to GEMM3)
__device__ float g_S[Bb*Ll*Hh];      // local (then full) n-sums
__device__ float g_cumd[Bb*Ll*Nn];   // within-chunk inclusive cumsum of delta
__device__ float g_hE[Bb*CH*Nn*Hh]; // chunk-end local states [b][k][n][c]
__device__ float g_h0[Bb*CH*Nn*Hh]; // chunk-start true states [b][k][n][c]

__device__ __forceinline__ float silu_(float x){ return x / (1.f + __expf(-x)); }
__device__ __forceinline__ float softplus_(float x){ return x > 20.f ? x : log1pf(__expf(x)); }
__device__ __forceinline__ float ex2f(float x){ float r; asm("ex2.approx.ftz.f32 %0, %1;" : "=f"(r) : "f"(x)); return r; }

// ---------------- 64x64-tile SGEMM, K=128, register-prefetch double buffering ------
// kb=1's global loads are issued immediately after kb=0's staging sync so they
// drain during kb=0's ~1000-cycle FMA block; only the first LDG wave is exposed.
template<int EPI>
__global__ __launch_bounds__(256) void gemm_kernel(
    const float* __restrict__ Ain, const float* __restrict__ Wp,
    const float* __restrict__ bias, float* __restrict__ Cout, int ldN)
{
    __shared__ __align__(16) float As[64][68];   // [row][k]
    __shared__ __align__(16) float Bs[64][64];   // [k][col]
    const float* Ap = (EPI == 1) ? Ain : (EPI == 2 ? g_xc : g_y);

    int tid = threadIdx.x;
    int ty = tid >> 4, tx = tid & 15;
    int row0 = blockIdx.x * 64;
    int col0 = blockIdx.y * 64;

    int ra = (tid + 0 * 256) >> 4;         // A-staging row per i handled below
    float acc[4][4];
    #pragma unroll
    for (int i = 0; i < 4; i++)
        #pragma unroll
        for (int j = 0; j < 4; j++) acc[i][j] = 0.f;
    (void)ra;

    float4 pA[4], pB[4];
    #pragma unroll
    for (int i = 0; i < 4; ++i) {
        int f = tid + i * 256;
        int r = f >> 4, kq = f & 15;
        pA[i] = *(const float4*)&Ap[(size_t)(row0 + r) * 128 + 0 * 64 + kq * 4];
    }
    #pragma unroll
    for (int i = 0; i < 4; ++i) {
        int f = tid + i * 256;
        int k = f >> 4, nq = f & 15;
        pB[i] = *(const float4*)&Wp[(size_t)(0 * 64 + k) * ldN + col0 + nq * 4];
    }

    #pragma unroll
    for (int kb = 0; kb < 2; ++kb) {
        #pragma unroll
        for (int i = 0; i < 4; ++i) {
            int f = tid + i * 256;
            int r = f >> 4, kq = f & 15;
            *(float4*)&As[r][kq * 4] = pA[i];
        }
        #pragma unroll
        for (int i = 0; i < 4; ++i) {
            int f = tid + i * 256;
            int k = f >> 4, nq = f & 15;
            *(float4*)&Bs[k][nq * 4] = pB[i];
        }
        __syncthreads();

        if (kb == 0) {
            // prefetch kb=1 while computing kb=0
            #pragma unroll
            for (int i = 0; i < 4; ++i) {
                int f = tid + i * 256;
                int r = f >> 4, kq = f & 15;
                pA[i] = *(const float4*)&Ap[(size_t)(row0 + r) * 128 + 64 + kq * 4];
            }
            #pragma unroll
            for (int i = 0; i < 4; ++i) {
                int f = tid + i * 256;
                int k = f >> 4, nq = f & 15;
                pB[i] = *(const float4*)&Wp[(size_t)(64 + k) * ldN + col0 + nq * 4];
            }
        }

        #pragma unroll 16
        for (int k = 0; k < 64; ++k) {
            float4 bv = *(float4*)&Bs[k][tx * 4];
            float a0 = As[ty * 4 + 0][k];
            float a1 = As[ty * 4 + 1][k];
            float a2 = As[ty * 4 + 2][k];
            float a3 = As[ty * 4 + 3][k];
            acc[0][0] = fmaf(a0, bv.x, acc[0][0]); acc[0][1] = fmaf(a0, bv.y, acc[0][1]);
            acc[0][2] = fmaf(a0, bv.z, acc[0][2]); acc[0][3] = fmaf(a0, bv.w, acc[0][3]);
            acc[1][0] = fmaf(a1, bv.x, acc[1][0]); acc[1][1] = fmaf(a1, bv.y, acc[1][1]);
            acc[1][2] = fmaf(a1, bv.z, acc[1][2]); acc[1][3] = fmaf(a1, bv.w, acc[1][3]);
            acc[2][0] = fmaf(a2, bv.x, acc[2][0]); acc[2][1] = fmaf(a2, bv.y, acc[2][1]);
            acc[2][2] = fmaf(a2, bv.z, acc[2][2]); acc[2][3] = fmaf(a2, bv.w, acc[2][3]);
            acc[3][0] = fmaf(a3, bv.x, acc[3][0]); acc[3][1] = fmaf(a3, bv.y, acc[3][1]);
            acc[3][2] = fmaf(a3, bv.z, acc[3][2]); acc[3][3] = fmaf(a3, bv.w, acc[3][3]);
        }
        __syncthreads();
    }

    #pragma unroll
    for (int i = 0; i < 4; ++i) {
        int row = row0 + ty * 4 + i;
        #pragma unroll
        for (int j = 0; j < 4; ++j) {
            int col = col0 + tx * 4 + j;
            float v = acc[i][j] + bias[col];
            if (EPI == 1) {
                if (col < 128) g_x[(size_t)row * 128 + col] = v;
                else           g_zs[(size_t)row * 128 + col - 128] = silu_(v);
            } else if (EPI == 2) {
                if (col < 128)      g_delta[(size_t)row * 128 + col] = softplus_(v);
                else if (col < 256) g_Braw[(size_t)row * 128 + col - 128] = v;
                else                g_C[(size_t)row * 128 + col - 256] = v;
            } else {
                Cout[(size_t)row * 128 + col] = v;
            }
        }
    }
}

// ---------------- depthwise conv3 (+bias, silu) ----------------
__global__ void conv_kernel(const float* __restrict__ cw, const float* __restrict__ cb)
{
    int idx = blockIdx.x * blockDim.x + threadIdx.x;
    if (idx >= Bb * Ll * Ee) return;
    int e = idx & 127;
    int t = (idx >> 7) & (Ll - 1);
    float w0 = cw[e * 3 + 0], w1 = cw[e * 3 + 1], w2 = cw[e * 3 + 2];
    float xm = g_x[idx];
    float xl = (t > 0)      ? g_x[idx - 128] : 0.f;
    float xr = (t < Ll - 1) ? g_x[idx + 128] : 0.f;
    float v = fmaf(w0, xl, fmaf(w1, xm, fmaf(w2, xr, cb[e])));
    g_xc[idx] = silu_(v);
}

// ---------------- Pass 1: per-chunk local scan (4n x 4c states per thread) ----------
__global__ __launch_bounds__(256) void scan_local_kernel(const float* __restrict__ A_log)
{
    __shared__ __align__(16) float smd[16][128];
    __shared__ __align__(16) float smb[16][128];
    __shared__ __align__(16) float smx[16][32];
    __shared__ float smP[4][32][33];

    int b  = blockIdx.z;
    int k  = blockIdx.y;
    int cg = blockIdx.x;
    int tid = threadIdx.x;
    int w = tid >> 5, ln = tid & 31;

    float Ac2[4];
    #pragma unroll
    for (int j = 0; j < 4; ++j)
        Ac2[j] = -__expf(A_log[cg * 32 + w * 4 + j]) * 1.44269504f;

    const float4* del4 = (const float4*)(g_delta + (size_t)b * Ll * Nn);
    const float4* br4  = (const float4*)(g_Braw  + (size_t)b * Ll * Nn);
    const float* xcb   = g_xc + (size_t)b * Ll * Ee + cg * 32;

    float h[4][4];
    #pragma unroll
    for (int j = 0; j < 4; ++j)
        #pragma unroll
        for (int i = 0; i < 4; ++i) h[j][i] = 0.f;

    float dc = 0.f;
    bool do_cum = (cg == 0) && (tid < 128);

    for (int t0 = k * CS; t0 < (k + 1) * CS; t0 += 16) {
        #pragma unroll
        for (int i = 0; i < 2; ++i) {
            int idx = tid + i * 256;
            float4 d = del4[t0 * 32 + idx];
            float4 r = br4[t0 * 32 + idx];
            ((float4*)smd)[idx] = d;
            float4 p; p.x = d.x * r.x; p.y = d.y * r.y; p.z = d.z * r.z; p.w = d.w * r.w;
            ((float4*)smb)[idx] = p;
        }
        if (tid < 128) {
            int tt = tid >> 3, q = tid & 7;
            *(float4*)&smx[tt][q * 4] = *(const float4*)&xcb[(size_t)(t0 + tt) * Ee + q * 4];
        }
        __syncthreads();

        if (do_cum) {
            float* gout = g_cumd + (size_t)b * Ll * Nn + (size_t)t0 * Nn + tid;
            #pragma unroll
            for (int tl = 0; tl < 16; ++tl) { dc += smd[tl][tid]; gout[tl * 128] = dc; }
        }

        #pragma unroll
        for (int tb = 0; tb < 16; tb += 4) {
            #pragma unroll
            for (int tt = 0; tt < 4; ++tt) {
                int t = tb + tt;
                float4 d4 = *(float4*)&smd[t][ln * 4];
                float4 b4 = *(float4*)&smb[t][ln * 4];
                float4 x4 = *(float4*)&smx[t][w * 4];
                float dn[4] = {d4.x, d4.y, d4.z, d4.w};
                float bn[4] = {b4.x, b4.y, b4.z, b4.w};
                float xs[4] = {x4.x, x4.y, x4.z, x4.w};
                #pragma unroll
                for (int j = 0; j < 4; ++j) {
                    #pragma unroll
                    for (int i = 0; i < 4; ++i) {
                        float e = ex2f(dn[i] * Ac2[j]);
                        h[j][i] = fmaf(e, h[j][i], bn[i] * xs[j]);
                    }
                    smP[tt][ln][w * 4 + j] = (h[j][0] + h[j][1]) + (h[j][2] + h[j][3]);
                }
            }
            __syncthreads();
            if (tid < 128) {
                int tt = tid >> 5, c = tid & 31;
                float s = 0.f;
                #pragma unroll
                for (int q = 0; q < 32; ++q) s += smP[tt][q][c];
                int t = t0 + tb + tt;
                g_S[(size_t)b * Ll * Hh + (size_t)t * Hh + cg * 32 + c] = s;
            }
            __syncthreads();
        }
    }

    size_t base = ((size_t)(b * CH + k) * Nn + ln * 4) * Hh + cg * 32 + w * 4;
    #pragma unroll
    for (int i = 0; i < 4; ++i) {
        float4 v; v.x = h[0][i]; v.y = h[1][i]; v.z = h[2][i]; v.w = h[3][i];
        *(float4*)&g_hE[base + (size_t)i * Hh] = v;
    }
}

// ---------------- Pass 2: inter-chunk state chain (grouped batched loads) ----------
__global__ __launch_bounds__(256) void chain_kernel(const float* __restrict__ A_log)
{
    int g = blockIdx.x * 256 + threadIdx.x;        // 0 .. 65535
    int c = g & 127, n = (g >> 7) & 127, b = g >> 14;
    float Ac2 = -__expf(A_log[c]) * 1.44269504f;
    const float* cd = g_cumd + (size_t)b * Ll * Nn + n;
    size_t base = ((size_t)(b * CH) * Nn + n) * Hh + c;   // k stride = Nn*Hh

    float h = 0.f;
    #pragma unroll
    for (int grp = 0; grp < CH / CG; ++grp) {
        int k0 = grp * CG;
        float dec[CG], hE[CG];
        #pragma unroll
        for (int k = 0; k < CG; ++k)
            dec[k] = cd[(size_t)((k0 + k) * CS + CS - 1) * Nn];
        #pragma unroll
        for (int k = 0; k < CG; ++k)
            hE[k] = g_hE[base + (size_t)(k0 + k) * (Nn * Hh)];
        #pragma unroll
        for (int k = 0; k < CG; ++k)
            dec[k] = ex2f(Ac2 * dec[k]);
        #pragma unroll
        for (int k = 0; k < CG; ++k) {
            g_h0[base + (size_t)(k0 + k) * (Nn * Hh)] = h;
            h = fmaf(dec[k], h, hE[k]);
        }
    }
}

// ---------------- Pass 3: fixup + combine ----------------
#define T3 8
__global__ __launch_bounds__(256) void fixup_kernel(
    const float* __restrict__ A_log, const float* __restrict__ Dv,
    const float* __restrict__ u)
{
    __shared__ __align__(16) float smh[32][128];
    __shared__ __align__(16) float smc[T3][128];

    int b = blockIdx.z, k = blockIdx.y, tg = blockIdx.x;
    int t0 = k * CS + tg * T3;
    int tid = threadIdx.x;
    int c = tid & 127, th = tid >> 7;

    float acc[4] = {0.f, 0.f, 0.f, 0.f};

    if (k > 0) {
        float Ac2 = -__expf(A_log[c]) * 1.44269504f;
        #pragma unroll
        for (int i = 0; i < 4; ++i) {
            int idx = tid + i * 256;
            int tt = idx >> 7, n = idx & 127;
            smc[tt][n] = g_cumd[(size_t)b * Ll * Nn + (size_t)(t0 + tt) * Nn + n];
        }
        const float4* h0p = (const float4*)(g_h0 + ((size_t)(b * CH + k) * Nn) * Hh);
        #pragma unroll
        for (int nb = 0; nb < 4; ++nb) {
            __syncthreads();
            #pragma unroll
            for (int i = 0; i < 4; ++i) {
                int idx = tid + i * 256;
                ((float4*)smh)[idx] = h0p[nb * 1024 + idx];
            }
            __syncthreads();
            #pragma unroll
            for (int n = 0; n < 32; ++n) {
                float hv = smh[n][c];
                #pragma unroll
                for (int j = 0; j < 4; ++j) {
                    float dl = smc[th * 4 + j][nb * 32 + n];
                    acc[j] = fmaf(ex2f(dl * Ac2), hv, acc[j]);
                }
            }
        }
    }

    #pragma unroll
    for (int j = 0; j < 4; ++j) {
        int t = t0 + th * 4 + j;
        size_t off = (size_t)b * Ll * Hh + (size_t)t * Hh + c;
        float S = g_S[off] + acc[j];
        float y = fmaf(S, g_C[off], Dv[c] * u[off]);
        g_y[off] = y * g_zs[off];
    }
}

// ---------------- launch ----------------
extern "C" void kernel_launch(void* const* d_in, const int* in_sizes, int n_in,
                              void* d_out, int out_size)
{
    const float* u      = (const float*)d_in[0];
    const float* W_in   = (const float*)d_in[1];
    const float* b_in   = (const float*)d_in[2];
    const float* conv_w = (const float*)d_in[3];
    const float* conv_b = (const float*)d_in[4];
    const float* W_x    = (const float*)d_in[5];
    const float* b_x    = (const float*)d_in[6];
    const float* A_log  = (const float*)d_in[7];
    const float* Dv     = (const float*)d_in[8];
    const float* W_out  = (const float*)d_in[9];
    const float* b_out  = (const float*)d_in[10];
    float* out = (float*)d_out;

    dim3 blk(256);
    gemm_kernel<1><<<dim3(ML / 64, 256 / 64), blk>>>(u, W_in, b_in, nullptr, 256);
    conv_kernel<<<(Bb * Ll * Ee + 255) / 256, blk>>>(conv_w, conv_b);
    gemm_kernel<2><<<dim3(ML / 64, 384 / 64), blk>>>(nullptr, W_x, b_x, nullptr, 384);
    scan_local_kernel<<<dim3(4, CH, Bb), blk>>>(A_log);
    chain_kernel<<<dim3(Bb * Nn * Hh / 256), blk>>>(A_log);
    fixup_kernel<<<dim3(CS / T3, CH, Bb), blk>>>(A_log, Dv, u);
    gemm_kernel<3><<<dim3(ML / 64, 128 / 64), blk>>>(nullptr, W_out, b_out, out, 128);
}